// round 5
// baseline (speedup 1.0000x reference)
#include <cuda_runtime.h>

#define NG      1024
#define IMG_W   256
#define IMG_H   256
#define TILE_SZ 64
#define FOCALF  256.0f
#define LOG2E   1.4426950408889634f

#define BLK_W   16
#define BLK_H   16
#define PAD     2.0f
#define NBLK    ((IMG_W / BLK_W) * (IMG_H / BLK_H))   // 256

// ---------------- device scratch ----------------
__device__ float4 g_A[NG];      // (mx, my, k*log2e, opacity)
__device__ float4 g_B[NG];      // (r, g, b, depth)
__device__ float4 g_R[NG];      // clamped rect
__device__ unsigned long long g_key[NG];

// ---------------- 1) project all gaussians once ----------------
__global__ void k_project(const float* __restrict__ means3d,
                          const float* __restrict__ opacity,
                          const float* __restrict__ scale3d,
                          const float* __restrict__ features,
                          const float* __restrict__ V,
                          const float* __restrict__ P) {
    int g = blockIdx.x * blockDim.x + threadIdx.x;
    if (g >= NG) return;
    float x = means3d[3*g+0], y = means3d[3*g+1], z = means3d[3*g+2];

    float pv0 = x*V[0] + y*V[4] + z*V[8]  + V[12];
    float pv1 = x*V[1] + y*V[5] + z*V[9]  + V[13];
    float pv2 = x*V[2] + y*V[6] + z*V[10] + V[14];
    float pv3 = x*V[3] + y*V[7] + z*V[11] + V[15];

    float ph0 = pv0*P[0] + pv1*P[4] + pv2*P[8]  + pv3*P[12];
    float ph1 = pv0*P[1] + pv1*P[5] + pv2*P[9]  + pv3*P[13];
    float ph3 = pv0*P[3] + pv1*P[7] + pv2*P[11] + pv3*P[15];

    float invw = __fdividef(1.0f, ph3 + 1e-6f);
    float mx = ((ph0*invw + 1.0f) * (float)IMG_W - 1.0f) * 0.5f;
    float my = ((ph1*invw + 1.0f) * (float)IMG_H - 1.0f) * 0.5f;

    float tz    = pv2;
    float s2    = scale3d[g] * FOCALF * __fdividef(1.0f, tz);
    float radii = s2 * 5.0f;
    float k2    = __fdividef(-0.5f * LOG2E, s2 * s2);

    float rminx = fminf(fmaxf(mx - radii, 0.0f), (float)IMG_W - 1.0f);
    float rminy = fminf(fmaxf(my - radii, 0.0f), (float)IMG_H - 1.0f);
    float rmaxx = fminf(fmaxf(mx + radii, 0.0f), (float)IMG_W - 1.0f);
    float rmaxy = fminf(fmaxf(my + radii, 0.0f), (float)IMG_H - 1.0f);

    g_A[g] = make_float4(mx, my, k2, opacity[g]);
    g_B[g] = make_float4(features[3*g+0], features[3*g+1], features[3*g+2], tz);
    g_R[g] = make_float4(rminx, rminy, rmaxx, rmaxy);

    unsigned ku = __float_as_uint(tz);
    ku = (ku & 0x80000000u) ? ~ku : (ku | 0x80000000u);
    g_key[g] = ((unsigned long long)ku << 32) | (unsigned)g;   // unique, stable
}

// ---------------- 2) render: 256 blocks x 512 threads, 2 threads/pixel ----------------
__global__ void __launch_bounds__(512) k_render(float* __restrict__ out) {
    __shared__ float4 sA[NG];
    __shared__ float4 sB[NG];
    __shared__ unsigned long long sKey[NG];
    __shared__ int s_cnt;
    __shared__ float xb[5][256];   // back-half partials: cr,cg,cb,dsum,T

    const int tid = threadIdx.x;
    const int bx  = blockIdx.x & 15;
    const int by  = blockIdx.x >> 4;
    const int x0  = bx * BLK_W;
    const int y0  = by * BLK_H;

    const float tu0 = (float)((x0 / TILE_SZ) * TILE_SZ);
    const float tv0 = (float)((y0 / TILE_SZ) * TILE_SZ);
    const float tu1 = tu0 + (float)TILE_SZ - 1.0f;
    const float tv1 = tv0 + (float)TILE_SZ - 1.0f;
    const float su0 = (float)x0 - PAD;
    const float su1 = (float)(x0 + BLK_W - 1) + PAD;
    const float sv0 = (float)y0 - PAD;
    const float sv1 = (float)(y0 + BLK_H - 1) + PAD;

    if (tid == 0) s_cnt = 0;
    __syncthreads();

    // ---- cull: 2 gaussians/thread, warp-aggregated compaction ----
    float4 mA[2], mB[2];
    unsigned long long mK[2];
    int nOwn = 0;
    const int lane = tid & 31;

    #pragma unroll
    for (int it = 0; it < 2; it++) {
        int g = tid + it * 512;
        float4 R = g_R[g];
        bool m = (fminf(R.z, tu1) > fmaxf(R.x, tu0)) &&
                 (fminf(R.w, tv1) > fmaxf(R.y, tv0)) &&
                 (fminf(R.z, su1) > fmaxf(R.x, su0)) &&
                 (fminf(R.w, sv1) > fmaxf(R.y, sv0));
        unsigned bal = __ballot_sync(0xffffffffu, m);
        if (m) {
            int prefix = __popc(bal & ((1u << lane) - 1u));
            int leader = __ffs(bal) - 1;
            int wbase = 0;
            if (lane == leader) wbase = atomicAdd(&s_cnt, __popc(bal));
            wbase = __shfl_sync(bal, wbase, leader);
            unsigned long long k = g_key[g];
            sKey[wbase + prefix] = k;
            mK[nOwn] = k;
            mA[nOwn] = g_A[g];     // prefetch now, consume after rank
            mB[nOwn] = g_B[g];
            nOwn++;
        }
    }
    __syncthreads();
    const int cnt = s_cnt;

    // ---- depth-rank placement (unique keys -> perfect permutation) ----
    for (int o = 0; o < nOwn; o++) {
        unsigned long long k = mK[o];
        int r = 0;
        for (int j = 0; j < cnt; j++) r += (sKey[j] < k) ? 1 : 0;
        sA[r] = mA[o];
        sB[r] = mB[o];
    }
    __syncthreads();

    // ---- split-list composite: 2 threads per pixel ----
    const int pxi = tid & 255;
    const int px  = x0 + (pxi & 15);
    const int py  = y0 + (pxi >> 4);
    const float fx = (float)px, fy = (float)py;
    const bool back = (tid >= 256);

    const int half = (cnt + 1) >> 1;
    int j0 = back ? half : 0;
    int j1 = back ? cnt : half;

    float T = 1.0f, cr = 0.0f, cg = 0.0f, cb = 0.0f, dsum = 0.0f;

    #pragma unroll 4
    for (int j = j0; j < j1; j++) {
        float4 A = sA[j];
        float dx = fx - A.x;
        float dy = fy - A.y;
        float d2 = fmaf(dx, dx, dy * dy);
        float e;
        asm("ex2.approx.ftz.f32 %0, %1;" : "=f"(e) : "f"(A.z * d2));
        float a = fminf(e * A.w, 0.99f);
        float w = a * T;
        float4 B = sB[j];
        cr   = fmaf(w, B.x, cr);
        cg   = fmaf(w, B.y, cg);
        cb   = fmaf(w, B.z, cb);
        dsum = fmaf(w, B.w, dsum);
        T    = T * (1.0f - a);
    }

    if (back) {
        xb[0][pxi] = cr;
        xb[1][pxi] = cg;
        xb[2][pxi] = cb;
        xb[3][pxi] = dsum;
        xb[4][pxi] = T;
    }
    __syncthreads();

    if (!back) {
        // (C,T) o (C',T') = (C + T*C', T*T')  -- exact over-operator composition
        cr   = fmaf(T, xb[0][pxi], cr);
        cg   = fmaf(T, xb[1][pxi], cg);
        cb   = fmaf(T, xb[2][pxi], cb);
        dsum = fmaf(T, xb[3][pxi], dsum);
        T    = T * xb[4][pxi];

        float acc = 1.0f - T;
        float bg  = T;
        int pix = py * IMG_W + px;
        out[pix*3 + 0] = fminf(fmaxf(cr + bg, 0.0f), 1.0f);
        out[pix*3 + 1] = fminf(fmaxf(cg + bg, 0.0f), 1.0f);
        out[pix*3 + 2] = fminf(fmaxf(cb + bg, 0.0f), 1.0f);
        out[IMG_W*IMG_H*3 + pix] = dsum;
        out[IMG_W*IMG_H*4 + pix] = acc;
    }
}

extern "C" void kernel_launch(void* const* d_in, const int* in_sizes, int n_in,
                              void* d_out, int out_size) {
    const float* means3d  = (const float*)d_in[0];
    const float* opacity  = (const float*)d_in[1];
    const float* scale3d  = (const float*)d_in[2];
    const float* features = (const float*)d_in[3];
    const float* viewm    = (const float*)d_in[4];
    const float* projm    = (const float*)d_in[5];
    float* out = (float*)d_out;

    k_project<<<4, 256>>>(means3d, opacity, scale3d, features, viewm, projm);
    k_render<<<NBLK, 512>>>(out);
}

// round 6
// speedup vs baseline: 1.2381x; 1.2381x over previous
#include <cuda_runtime.h>

#define NG      1024
#define IMG_W   256
#define IMG_H   256
#define TILE_SZ 64
#define FOCALF  256.0f
#define LOG2E   1.4426950408889634f

#define BLK_W   32
#define BLK_H   16
#define PAD     2.0f
#define NBLK    ((IMG_W / BLK_W) * (IMG_H / BLK_H))   // 8 x 16 = 128
#define NPX     (BLK_W * BLK_H)                        // 512

__device__ __forceinline__ float frcp(float x) {
    float r; asm("rcp.approx.ftz.f32 %0, %1;" : "=f"(r) : "f"(x)); return r;
}
__device__ __forceinline__ float flg2(float x) {
    float r; asm("lg2.approx.f32 %0, %1;" : "=f"(r) : "f"(x)); return r;
}
__device__ __forceinline__ float fex2(float x) {
    float r; asm("ex2.approx.ftz.f32 %0, %1;" : "=f"(r) : "f"(x)); return r;
}

// Single fused kernel: 128 blocks x 1024 threads. Each block renders 32x16 px
// with 2 threads/pixel (split-list exact compositing). Projection: 1 gaussian
// per thread using a precomputed fused coefficient matrix M (16 floats).
__global__ void __launch_bounds__(1024) k_fused(
        const float* __restrict__ means3d,
        const float* __restrict__ opacity,
        const float* __restrict__ scale3d,
        const float* __restrict__ features,
        const float* __restrict__ V,
        const float* __restrict__ P,
        float* __restrict__ out) {

    __shared__ float4 sA[NG];        // (mx, my, k2, lg2(op))    16 KB
    __shared__ float4 sB[NG];        // (r, g, b, depth)         16 KB
    // keys are dead after the rank phase; the combine buffer reuses the space
    __shared__ unsigned long long uKey[NPX * 5 * 4 / 8];   // 10240 B
    __shared__ float M[16];
    __shared__ int s_cnt;

    unsigned long long* sKey = uKey;            // [NG] during cull/rank... (capped below)
    float* xb = (float*)uKey;                   // [5][NPX] during combine

    const int tid = threadIdx.x;

    // fused projection coefficients: groups (ph0, ph1, ph3, tz) x (x,y,z,1)
    if (tid < 16) {
        int r = tid & 3, c = tid >> 2;
        float m;
        if (c < 3) {
            int pc = (c == 2) ? 3 : c;
            m = V[r*4+0]*P[0*4+pc] + V[r*4+1]*P[1*4+pc]
              + V[r*4+2]*P[2*4+pc] + V[r*4+3]*P[3*4+pc];
        } else {
            m = V[r*4+2];            // tz = view column 2
        }
        M[c*4 + (tid & 3)] = m;      // M[c][r]
    }
    if (tid == 0) s_cnt = 0;

    const int bx = blockIdx.x & 7;
    const int by = blockIdx.x >> 3;
    const int x0 = bx * BLK_W;
    const int y0 = by * BLK_H;

    const float tu0 = (float)((x0 / TILE_SZ) * TILE_SZ);
    const float tv0 = (float)((y0 / TILE_SZ) * TILE_SZ);
    const float tu1 = tu0 + (float)TILE_SZ - 1.0f;
    const float tv1 = tv0 + (float)TILE_SZ - 1.0f;
    const float su0 = (float)x0 - PAD;
    const float su1 = (float)(x0 + BLK_W - 1) + PAD;
    const float sv0 = (float)y0 - PAD;
    const float sv1 = (float)(y0 + BLK_H - 1) + PAD;

    __syncthreads();

    // ---- project + cull: gaussian g == tid ----
    float x  = means3d[3*tid+0];
    float y  = means3d[3*tid+1];
    float z  = means3d[3*tid+2];
    float sc = scale3d[tid];

    float ph0 = fmaf(x, M[0],  fmaf(y, M[1],  fmaf(z, M[2],  M[3])));
    float ph1 = fmaf(x, M[4],  fmaf(y, M[5],  fmaf(z, M[6],  M[7])));
    float ph3 = fmaf(x, M[8],  fmaf(y, M[9],  fmaf(z, M[10], M[11])));
    float tz  = fmaf(x, M[12], fmaf(y, M[13], fmaf(z, M[14], M[15])));

    float invw = frcp(ph3 + 1e-6f);
    float mx = fmaf(ph0 * invw, 128.0f, 127.5f);
    float my = fmaf(ph1 * invw, 128.0f, 127.5f);

    float rtz   = frcp(tz);
    float s2    = sc * FOCALF * rtz;
    float radii = 5.0f * s2;
    float rs2   = frcp(s2);
    float k2    = (-0.5f * LOG2E) * rs2 * rs2;

    float rminx = fminf(fmaxf(mx - radii, 0.0f), (float)IMG_W - 1.0f);
    float rminy = fminf(fmaxf(my - radii, 0.0f), (float)IMG_H - 1.0f);
    float rmaxx = fminf(fmaxf(mx + radii, 0.0f), (float)IMG_W - 1.0f);
    float rmaxy = fminf(fmaxf(my + radii, 0.0f), (float)IMG_H - 1.0f);

    bool m = (fminf(rmaxx, tu1) > fmaxf(rminx, tu0)) &&   // exact reference tile mask
             (fminf(rmaxy, tv1) > fmaxf(rminy, tv0)) &&
             (fminf(rmaxx, su1) > fmaxf(rminx, su0)) &&   // padded sub-rect cull
             (fminf(rmaxy, sv1) > fmaxf(rminy, sv0));

    const int lane = tid & 31;
    unsigned bal = __ballot_sync(0xffffffffu, m);
    unsigned long long myKey = 0;
    float lop = 0.0f, fr = 0.0f, fg = 0.0f, fb = 0.0f;
    if (m) {
        int prefix = __popc(bal & ((1u << lane) - 1u));
        int leader = __ffs(bal) - 1;
        int wbase = 0;
        if (lane == leader) wbase = atomicAdd(&s_cnt, __popc(bal));
        wbase = __shfl_sync(bal, wbase, leader);
        unsigned ku = __float_as_uint(tz);
        ku = (ku & 0x80000000u) ? ~ku : (ku | 0x80000000u);
        myKey = ((unsigned long long)ku << 32) | (unsigned)tid;   // unique, stable
        sKey[wbase + prefix] = myKey;
        lop = flg2(opacity[tid]);           // winner-only loads
        fr = features[3*tid+0];
        fg = features[3*tid+1];
        fb = features[3*tid+2];
    }
    __syncthreads();
    const int cnt = s_cnt;

    // ---- depth-rank placement (unique keys -> perfect permutation) ----
    if (m) {
        int r = 0;
        for (int j = 0; j < cnt; j++) r += (sKey[j] < myKey) ? 1 : 0;
        sA[r] = make_float4(mx, my, k2, lop);
        sB[r] = make_float4(fr, fg, fb, tz);
    }
    __syncthreads();

    // ---- split-list composite: 2 threads per pixel ----
    const int pxi = tid & (NPX - 1);
    const int px  = x0 + (pxi & (BLK_W - 1));
    const int py  = y0 + (pxi / BLK_W);
    const float fx = (float)px, fy = (float)py;
    const bool back = (tid >= NPX);

    const int half = (cnt + 1) >> 1;
    const int j0 = back ? half : 0;
    const int j1 = back ? cnt : half;

    float T = 1.0f, cr = 0.0f, cg = 0.0f, cb = 0.0f, dsum = 0.0f;

    #pragma unroll 4
    for (int j = j0; j < j1; j++) {
        float4 A = sA[j];
        float dx  = fx - A.x;
        float dy  = fy - A.y;
        float d2  = fmaf(dx, dx, dy * dy);
        float a   = fminf(fex2(fmaf(A.z, d2, A.w)), 0.99f);   // min(op*gw, 0.99)
        float w   = a * T;
        float4 B = sB[j];
        cr   = fmaf(w, B.x, cr);
        cg   = fmaf(w, B.y, cg);
        cb   = fmaf(w, B.z, cb);
        dsum = fmaf(w, B.w, dsum);
        T    = fmaf(-a, T, T);
    }

    __syncthreads();             // keys fully dead -> reuse as xb
    if (back) {
        xb[0*NPX + pxi] = cr;
        xb[1*NPX + pxi] = cg;
        xb[2*NPX + pxi] = cb;
        xb[3*NPX + pxi] = dsum;
        xb[4*NPX + pxi] = T;
    }
    __syncthreads();

    if (!back) {
        // (C,T) o (C',T') = (C + T*C', T*T')  -- exact composition
        cr   = fmaf(T, xb[0*NPX + pxi], cr);
        cg   = fmaf(T, xb[1*NPX + pxi], cg);
        cb   = fmaf(T, xb[2*NPX + pxi], cb);
        dsum = fmaf(T, xb[3*NPX + pxi], dsum);
        T    = T * xb[4*NPX + pxi];

        float acc = 1.0f - T;
        float bg  = T;
        int pix = py * IMG_W + px;
        out[pix*3 + 0] = fminf(fmaxf(cr + bg, 0.0f), 1.0f);
        out[pix*3 + 1] = fminf(fmaxf(cg + bg, 0.0f), 1.0f);
        out[pix*3 + 2] = fminf(fmaxf(cb + bg, 0.0f), 1.0f);
        out[IMG_W*IMG_H*3 + pix] = dsum;
        out[IMG_W*IMG_H*4 + pix] = acc;
    }
}

extern "C" void kernel_launch(void* const* d_in, const int* in_sizes, int n_in,
                              void* d_out, int out_size) {
    const float* means3d  = (const float*)d_in[0];
    const float* opacity  = (const float*)d_in[1];
    const float* scale3d  = (const float*)d_in[2];
    const float* features = (const float*)d_in[3];
    const float* viewm    = (const float*)d_in[4];
    const float* projm    = (const float*)d_in[5];
    float* out = (float*)d_out;

    k_fused<<<NBLK, 1024>>>(means3d, opacity, scale3d, features, viewm, projm, out);
}